// round 9
// baseline (speedup 1.0000x reference)
#include <cuda_runtime.h>
#include <cuda_bf16.h>
#include <cuda_fp16.h>
#include <cstdint>

// Problem constants (fixed by the dataset)
#define NMAX 50000
#define CIN  128
#define C2   256
#define COUT 128
#define KNB  16

// Scratch (static device arrays; no allocation):
// g_eq[node]: 256 half = e = exp(z), then 256 half = q = e*y  (1KB per node)
__device__ __half g_eq[(size_t)NMAX * 512];
__device__ __nv_bfloat16 g_W1h[256 * 128];        // W1^T hi  [n][k]
__device__ __nv_bfloat16 g_W1l[256 * 128];        // W1^T lo
__device__ __nv_bfloat16 g_Wsh[256 * 256];        // Ws^T hi  [n][k]
__device__ __nv_bfloat16 g_Wsl[256 * 256];        // Ws^T lo
__device__ __nv_bfloat16 g_Wmh[128 * 256];        // Wm^T hi  [n][k]
__device__ __nv_bfloat16 g_Wml[128 * 256];        // Wm^T lo
__device__ int g_idx64;

// ---------------------------------------------------------------------------
// mma.sync m16n8k16 bf16 (baseline PTX, valid on compute_103 virtual arch)
// ---------------------------------------------------------------------------
__device__ __forceinline__ void mma16816(float* d,
    uint32_t a0, uint32_t a1, uint32_t a2, uint32_t a3,
    uint32_t b0, uint32_t b1)
{
    asm volatile(
        "mma.sync.aligned.m16n8k16.row.col.f32.bf16.bf16.f32 "
        "{%0,%1,%2,%3}, {%4,%5,%6,%7}, {%8,%9}, {%0,%1,%2,%3};"
        : "+f"(d[0]), "+f"(d[1]), "+f"(d[2]), "+f"(d[3])
        : "r"(a0), "r"(a1), "r"(a2), "r"(a3), "r"(b0), "r"(b1));
}

// SMEM layout for kernelA (bytes). Strides 272/528 ≡ 4 mod 32 words.
#define XS   272
#define XH_OFF 0
#define XL_OFF 17408              // 64*272
#define YS   528
#define YSH_OFF 0
#define YSL_OFF 33792             // 64*528
#define WS   272
#define W_OFF 69632
#define WHL  69632                // 256*272
#define PAR_OFF 208896
#define SMEM_TOTAL 212992

// ---------------------------------------------------------------------------
// Prep: pack W1^T, Ws^T, Wm^T bf16 hi/lo, [n][k]; idx dtype detect. 32 blocks.
// ---------------------------------------------------------------------------
__global__ __launch_bounds__(256) void prep_kernel(
    const float* __restrict__ W1,
    const float* __restrict__ Ws,
    const float* __restrict__ Wm,
    const unsigned int* __restrict__ idxraw)
{
    const int b = blockIdx.x, tid = threadIdx.x;
    if (b == 0 && tid == 0) {   // int64 -> every odd 32-bit word zero
        int is64 = 1;
        #pragma unroll 1
        for (int t = 1; t < 256; t += 2)
            if (idxraw[t] != 0u) { is64 = 0; break; }
        g_idx64 = is64;
    }
    if (b < 8) {                 // W1: 32768 elems
        #pragma unroll
        for (int i = 0; i < 16; i++) {
            int idx = b * 4096 + tid + i * 256;
            int k = idx >> 8, n = idx & 255;
            float v = W1[(size_t)k * 256 + n];
            __nv_bfloat16 hi = __float2bfloat16(v);
            g_W1h[n * 128 + k] = hi;
            g_W1l[n * 128 + k] = __float2bfloat16(v - __bfloat162float(hi));
        }
    } else if (b < 24) {         // Ws: 65536 elems
        #pragma unroll
        for (int i = 0; i < 16; i++) {
            int idx = (b - 8) * 4096 + tid + i * 256;
            int k = idx >> 8, n = idx & 255;
            float v = Ws[(size_t)k * 256 + n];
            __nv_bfloat16 hi = __float2bfloat16(v);
            g_Wsh[n * 256 + k] = hi;
            g_Wsl[n * 256 + k] = __float2bfloat16(v - __bfloat162float(hi));
        }
    } else {                     // Wm: 32768 elems (256k x 128n)
        #pragma unroll
        for (int i = 0; i < 16; i++) {
            int idx = (b - 24) * 4096 + tid + i * 256;
            int k = idx >> 7, n = idx & 127;
            float v = Wm[(size_t)k * 128 + n];
            __nv_bfloat16 hi = __float2bfloat16(v);
            g_Wmh[n * 256 + k] = hi;
            g_Wml[n * 256 + k] = __float2bfloat16(v - __bfloat162float(hi));
        }
    }
}

// ---------------------------------------------------------------------------
// kernelA_mma: block = 64 rows x 256 cols, 8 warps (4 M x 2 N).
// GEMM1 (X@W1, bf16 hi/lo 3-MMA) -> BN -> ys (smem) -> GEMM2 (ys@Ws)
// -> epilogue e=exp(z), q=e*y stored fp16 interleaved.  (unchanged, passing)
// ---------------------------------------------------------------------------
__global__ __launch_bounds__(256, 1) void kernelA_mma(
    const float* __restrict__ f,
    const float* __restrict__ b1, const float* __restrict__ gamma,
    const float* __restrict__ beta, const float* __restrict__ rmean,
    const float* __restrict__ rvar, int N)
{
    extern __shared__ unsigned char smem[];
    const int tid = threadIdx.x, wid = tid >> 5, lane = tid & 31;
    const int ms = wid & 3, nh = wid >> 2;
    const int g = lane >> 2, kt = lane & 3;
    const int row0 = blockIdx.x * 64;

    float* Pb  = (float*)(smem + PAR_OFF);
    float* Pinv = Pb + 256; float* Pmu = Pinv + 256; float* Pbt = Pmu + 256;
    {
        int c = tid;
        Pb[c]   = b1[c];
        Pinv[c] = gamma[c] * rsqrtf(rvar[c] + 1e-5f);
        Pmu[c]  = rmean[c];
        Pbt[c]  = beta[c];
    }

    // Stage X (64x128 f32 -> bf16 hi/lo)
    #pragma unroll
    for (int i = 0; i < 8; i++) {
        int fi = tid + i * 256;
        int r = fi >> 5, c4 = fi & 31;
        float4 v = make_float4(0.f, 0.f, 0.f, 0.f);
        if (row0 + r < N) v = ((const float4*)(f + (size_t)(row0 + r) * CIN))[c4];
        __nv_bfloat162 h0 = __floats2bfloat162_rn(v.x, v.y);
        __nv_bfloat162 h1 = __floats2bfloat162_rn(v.z, v.w);
        __nv_bfloat162 l0 = __floats2bfloat162_rn(v.x - __bfloat162float(h0.x),
                                                  v.y - __bfloat162float(h0.y));
        __nv_bfloat162 l1 = __floats2bfloat162_rn(v.z - __bfloat162float(h1.x),
                                                  v.w - __bfloat162float(h1.y));
        uint2 hu, lu;
        hu.x = *(uint32_t*)&h0; hu.y = *(uint32_t*)&h1;
        lu.x = *(uint32_t*)&l0; lu.y = *(uint32_t*)&l1;
        *(uint2*)(smem + XH_OFF + r * XS + c4 * 8) = hu;
        *(uint2*)(smem + XL_OFF + r * XS + c4 * 8) = lu;
    }
    // Stage W1
    #pragma unroll
    for (int i = 0; i < 32; i++) {
        int u = tid + i * 256;
        int half_ = u >> 12, r = (u >> 4) & 255, c = u & 15;
        const uint4* src = (const uint4*)(half_ ? (const void*)g_W1l : (const void*)g_W1h);
        *(uint4*)(smem + W_OFF + half_ * WHL + r * WS + c * 16) = src[r * 16 + c];
    }
    __syncthreads();

    float acc[16][4];
    #pragma unroll
    for (int t = 0; t < 16; t++)
        #pragma unroll
        for (int j = 0; j < 4; j++) acc[t][j] = 0.f;

    // GEMM 1: K = 128
    {
        const unsigned char* Ah = smem + XH_OFF + (16 * ms + g) * XS + kt * 4;
        const unsigned char* Al = smem + XL_OFF + (16 * ms + g) * XS + kt * 4;
        const unsigned char* Bb = smem + W_OFF + (nh * 128 + g) * WS + kt * 4;
        #pragma unroll 1
        for (int ks = 0; ks < 8; ks++) {
            const int kb = ks * 32;
            uint32_t ah0 = *(const uint32_t*)(Ah + kb);
            uint32_t ah1 = *(const uint32_t*)(Ah + kb + 8 * XS);
            uint32_t ah2 = *(const uint32_t*)(Ah + kb + 16);
            uint32_t ah3 = *(const uint32_t*)(Ah + kb + 8 * XS + 16);
            uint32_t al0 = *(const uint32_t*)(Al + kb);
            uint32_t al1 = *(const uint32_t*)(Al + kb + 8 * XS);
            uint32_t al2 = *(const uint32_t*)(Al + kb + 16);
            uint32_t al3 = *(const uint32_t*)(Al + kb + 8 * XS + 16);
            #pragma unroll
            for (int t = 0; t < 16; t++) {
                const unsigned char* Bp = Bb + t * 8 * WS + kb;
                uint32_t bh0 = *(const uint32_t*)(Bp);
                uint32_t bh1 = *(const uint32_t*)(Bp + 16);
                uint32_t bl0 = *(const uint32_t*)(Bp + WHL);
                uint32_t bl1 = *(const uint32_t*)(Bp + WHL + 16);
                mma16816(acc[t], ah0, ah1, ah2, ah3, bh0, bh1);
                mma16816(acc[t], ah0, ah1, ah2, ah3, bl0, bl1);
                mma16816(acc[t], al0, al1, al2, al3, bh0, bh1);
            }
        }
    }
    __syncthreads();

    // BN epilogue -> ys hi/lo (smem)
    #pragma unroll
    for (int t = 0; t < 16; t++) {
        const int nc0 = nh * 128 + t * 8 + 2 * kt;
        float2 pb  = *(const float2*)&Pb[nc0];
        float2 pin = *(const float2*)&Pinv[nc0];
        float2 pmu = *(const float2*)&Pmu[nc0];
        float2 pbt = *(const float2*)&Pbt[nc0];
        float y00 = (fmaxf(acc[t][0] + pb.x, 0.f) - pmu.x) * pin.x + pbt.x;
        float y01 = (fmaxf(acc[t][1] + pb.y, 0.f) - pmu.y) * pin.y + pbt.y;
        float y10 = (fmaxf(acc[t][2] + pb.x, 0.f) - pmu.x) * pin.x + pbt.x;
        float y11 = (fmaxf(acc[t][3] + pb.y, 0.f) - pmu.y) * pin.y + pbt.y;
        __nv_bfloat162 h0 = __floats2bfloat162_rn(y00, y01);
        __nv_bfloat162 h1 = __floats2bfloat162_rn(y10, y11);
        __nv_bfloat162 l0 = __floats2bfloat162_rn(y00 - __bfloat162float(h0.x),
                                                  y01 - __bfloat162float(h0.y));
        __nv_bfloat162 l1 = __floats2bfloat162_rn(y10 - __bfloat162float(h1.x),
                                                  y11 - __bfloat162float(h1.y));
        const int r0 = 16 * ms + g;
        *(uint32_t*)(smem + YSH_OFF + r0 * YS + nc0 * 2)       = *(uint32_t*)&h0;
        *(uint32_t*)(smem + YSH_OFF + (r0 + 8) * YS + nc0 * 2) = *(uint32_t*)&h1;
        *(uint32_t*)(smem + YSL_OFF + r0 * YS + nc0 * 2)       = *(uint32_t*)&l0;
        *(uint32_t*)(smem + YSL_OFF + (r0 + 8) * YS + nc0 * 2) = *(uint32_t*)&l1;
    }

    // GEMM 2: K = 256 in 2 staged chunks
    #pragma unroll
    for (int t = 0; t < 16; t++)
        #pragma unroll
        for (int j = 0; j < 4; j++) acc[t][j] = 0.f;

    #pragma unroll 1
    for (int chunk = 0; chunk < 2; chunk++) {
        __syncthreads();
        #pragma unroll
        for (int i = 0; i < 32; i++) {
            int u = tid + i * 256;
            int half_ = u >> 12, r = (u >> 4) & 255, c = u & 15;
            const unsigned char* src =
                (const unsigned char*)(half_ ? (const void*)g_Wsl : (const void*)g_Wsh)
                + (size_t)r * 512 + chunk * 256 + c * 16;
            *(uint4*)(smem + W_OFF + half_ * WHL + r * WS + c * 16) = *(const uint4*)src;
        }
        __syncthreads();

        const unsigned char* Ah = smem + YSH_OFF + (16 * ms + g) * YS + chunk * 256 + kt * 4;
        const unsigned char* Al = smem + YSL_OFF + (16 * ms + g) * YS + chunk * 256 + kt * 4;
        const unsigned char* Bb = smem + W_OFF + (nh * 128 + g) * WS + kt * 4;
        #pragma unroll 1
        for (int ks = 0; ks < 8; ks++) {
            const int kb = ks * 32;
            uint32_t ah0 = *(const uint32_t*)(Ah + kb);
            uint32_t ah1 = *(const uint32_t*)(Ah + kb + 8 * YS);
            uint32_t ah2 = *(const uint32_t*)(Ah + kb + 16);
            uint32_t ah3 = *(const uint32_t*)(Ah + kb + 8 * YS + 16);
            uint32_t al0 = *(const uint32_t*)(Al + kb);
            uint32_t al1 = *(const uint32_t*)(Al + kb + 8 * YS);
            uint32_t al2 = *(const uint32_t*)(Al + kb + 16);
            uint32_t al3 = *(const uint32_t*)(Al + kb + 8 * YS + 16);
            #pragma unroll
            for (int t = 0; t < 16; t++) {
                const unsigned char* Bp = Bb + t * 8 * WS + kb;
                uint32_t bh0 = *(const uint32_t*)(Bp);
                uint32_t bh1 = *(const uint32_t*)(Bp + 16);
                uint32_t bl0 = *(const uint32_t*)(Bp + WHL);
                uint32_t bl1 = *(const uint32_t*)(Bp + WHL + 16);
                mma16816(acc[t], ah0, ah1, ah2, ah3, bh0, bh1);
                mma16816(acc[t], ah0, ah1, ah2, ah3, bl0, bl1);
                mma16816(acc[t], al0, al1, al2, al3, bh0, bh1);
            }
        }
    }

    // Final epilogue: e = exp(z), q = e*y; fp16 interleaved stores
    #pragma unroll
    for (int t = 0; t < 16; t++) {
        const int nc0 = nh * 128 + t * 8 + 2 * kt;
        const int r0 = 16 * ms + g;
        uint32_t yh0 = *(const uint32_t*)(smem + YSH_OFF + r0 * YS + nc0 * 2);
        uint32_t yl0 = *(const uint32_t*)(smem + YSL_OFF + r0 * YS + nc0 * 2);
        uint32_t yh1 = *(const uint32_t*)(smem + YSH_OFF + (r0 + 8) * YS + nc0 * 2);
        uint32_t yl1 = *(const uint32_t*)(smem + YSL_OFF + (r0 + 8) * YS + nc0 * 2);
        __nv_bfloat162 h0 = *(__nv_bfloat162*)&yh0, l0 = *(__nv_bfloat162*)&yl0;
        __nv_bfloat162 h1 = *(__nv_bfloat162*)&yh1, l1 = *(__nv_bfloat162*)&yl1;
        float y00 = __bfloat162float(h0.x) + __bfloat162float(l0.x);
        float y01 = __bfloat162float(h0.y) + __bfloat162float(l0.y);
        float y10 = __bfloat162float(h1.x) + __bfloat162float(l1.x);
        float y11 = __bfloat162float(h1.y) + __bfloat162float(l1.y);
        float e00 = __expf(acc[t][0]), e01 = __expf(acc[t][1]);
        float e10 = __expf(acc[t][2]), e11 = __expf(acc[t][3]);
        int gr0 = row0 + r0, gr1 = gr0 + 8;
        if (gr0 < N) {
            *(__half2*)(g_eq + (size_t)gr0 * 512 + nc0)       = __floats2half2_rn(e00, e01);
            *(__half2*)(g_eq + (size_t)gr0 * 512 + 256 + nc0) = __floats2half2_rn(e00 * y00, e01 * y01);
        }
        if (gr1 < N) {
            *(__half2*)(g_eq + (size_t)gr1 * 512 + nc0)       = __floats2half2_rn(e10, e11);
            *(__half2*)(g_eq + (size_t)gr1 * 512 + 256 + nc0) = __floats2half2_rn(e10 * y10, e11 * y11);
        }
    }
}

// ---------------------------------------------------------------------------
// Kernel B: block = 8 nodes, 512 threads, 2 warps per node (role-split).
//   role 0: gather e-halves (16 LDG.128) -> den ; role 1: q-halves -> num.
//   Exchange via smem, feat = num/den -> bf16 hi/lo [16 rows; 8..15 zeroed]
//   Phase 2: m16n8k16 bf16 3-MMA split vs Wm; rows 8..15 discarded.
// ---------------------------------------------------------------------------
#define FS 528   // feat row stride bytes (264 bf16)
#define DSTR 264 // den/num row stride floats
__global__ __launch_bounds__(512, 3) void kernelB(
    const void* __restrict__ idxp,
    const float* __restrict__ bm,
    float* __restrict__ out,
    int N)
{
    __shared__ float sden[8][DSTR];                       // 8448 B
    __shared__ float snum[8][DSTR];                       // 8448 B
    __shared__ __align__(16) unsigned char sfeat[2 * 16 * FS];  // 16896 B

    const int tid  = threadIdx.x;
    const int w    = tid >> 5;
    const int lane = tid & 31;
    const int node = w >> 1;          // 0..7
    const int role = w & 1;           // 0 = e/den, 1 = q/num
    const int n    = blockIdx.x * 8 + node;
    const int ncl  = (n < N) ? n : (N - 1);

    const int is64 = g_idx64;

    int my = 0;
    if (lane < KNB) {
        if (is64) my = (int)((const long long*)idxp)[(size_t)ncl * KNB + lane];
        else      my = ((const int*)idxp)[(size_t)ncl * KNB + lane];
    }
    int nb[KNB];
    #pragma unroll
    for (int k = 0; k < KNB; k++)
        nb[k] = __shfl_sync(0xffffffffu, my, k);

    // Gather this role's half: 1 LDG.128 per neighbor (lane owns 8 channels)
    float acc[8];
    #pragma unroll
    for (int q = 0; q < 8; q++) acc[q] = 0.f;

    #pragma unroll 4
    for (int k = 0; k < KNB; k++) {
        const uint4* p = (const uint4*)(g_eq + (size_t)nb[k] * 512) + role * 32 + lane;
        uint4 v = *p;
        const __half2* h = (const __half2*)&v;
        #pragma unroll
        for (int j = 0; j < 4; j++) {
            float2 fv = __half22float2(h[j]);
            acc[2*j]   += fv.x;
            acc[2*j+1] += fv.y;
        }
    }

    {
        float* dst = (role ? &snum[node][0] : &sden[node][0]) + 8 * lane;
        *(float4*)(dst)     = make_float4(acc[0], acc[1], acc[2], acc[3]);
        *(float4*)(dst + 4) = make_float4(acc[4], acc[5], acc[6], acc[7]);
    }
    __syncthreads();

    // feat = num/den -> bf16 hi/lo smem (warps 0..7 = nodes; warps 8..15 zero)
    if (w < 8) {
        const float* dn = &sden[w][8 * lane];
        const float* nm = &snum[w][8 * lane];
        uint32_t hw[4], lw[4];
        #pragma unroll
        for (int j = 0; j < 4; j++) {
            float f0 = __fdividef(nm[2*j],   dn[2*j]);
            float f1 = __fdividef(nm[2*j+1], dn[2*j+1]);
            __nv_bfloat162 hh = __floats2bfloat162_rn(f0, f1);
            __nv_bfloat162 ll = __floats2bfloat162_rn(f0 - __bfloat162float(hh.x),
                                                      f1 - __bfloat162float(hh.y));
            hw[j] = *(uint32_t*)&hh;
            lw[j] = *(uint32_t*)&ll;
        }
        *(uint4*)(sfeat + w * FS + lane * 16)           = make_uint4(hw[0], hw[1], hw[2], hw[3]);
        *(uint4*)(sfeat + 16 * FS + w * FS + lane * 16) = make_uint4(lw[0], lw[1], lw[2], lw[3]);
    } else {
        // zero rows 8..15 (hi and lo) so phase-2 A-frags are well-defined
        *(uint4*)(sfeat + w * FS + lane * 16)           = make_uint4(0, 0, 0, 0);
        *(uint4*)(sfeat + 16 * FS + w * FS + lane * 16) = make_uint4(0, 0, 0, 0);
    }
    __syncthreads();

    // Phase 2: out(8 x 128) = feat(8 x 256) @ Wm; warp w -> cols w*8..w*8+7
    {
        const int g  = lane >> 2, kt = lane & 3;
        float accd[4] = {0.f, 0.f, 0.f, 0.f};

        const unsigned char* Ah = sfeat + g * FS + kt * 4;
        const unsigned char* Al = Ah + 16 * FS;
        const __nv_bfloat16* Bh = g_Wmh + (size_t)(w * 8 + g) * 256 + 2 * kt;
        const __nv_bfloat16* Bl = g_Wml + (size_t)(w * 8 + g) * 256 + 2 * kt;

        #pragma unroll 4
        for (int ks = 0; ks < 16; ks++) {
            const int kb = ks * 32;
            uint32_t ah0 = *(const uint32_t*)(Ah + kb);
            uint32_t ah1 = *(const uint32_t*)(Ah + kb + 8 * FS);
            uint32_t ah2 = *(const uint32_t*)(Ah + kb + 16);
            uint32_t ah3 = *(const uint32_t*)(Ah + kb + 8 * FS + 16);
            uint32_t al0 = *(const uint32_t*)(Al + kb);
            uint32_t al1 = *(const uint32_t*)(Al + kb + 8 * FS);
            uint32_t al2 = *(const uint32_t*)(Al + kb + 16);
            uint32_t al3 = *(const uint32_t*)(Al + kb + 8 * FS + 16);
            uint32_t bh0 = *(const uint32_t*)(Bh + ks * 16);
            uint32_t bh1 = *(const uint32_t*)(Bh + ks * 16 + 8);
            uint32_t bl0 = *(const uint32_t*)(Bl + ks * 16);
            uint32_t bl1 = *(const uint32_t*)(Bl + ks * 16 + 8);
            mma16816(accd, ah0, ah1, ah2, ah3, bh0, bh1);
            mma16816(accd, ah0, ah1, ah2, ah3, bl0, bl1);
            mma16816(accd, al0, al1, al2, al3, bh0, bh1);
        }

        // Valid D rows = g (nodes 0..7); rows g+8 are the zeroed dummies.
        if (g < 8) {
            const int c0 = w * 8 + 2 * kt;
            float2 bb = *(const float2*)(bm + c0);
            int n0 = blockIdx.x * 8 + g;
            if (n0 < N)
                *(float2*)(out + (size_t)n0 * COUT + c0) =
                    make_float2(accd[0] + bb.x, accd[1] + bb.y);
        }
    }
}

// ---------------------------------------------------------------------------
// Launch
// ---------------------------------------------------------------------------
extern "C" void kernel_launch(void* const* d_in, const int* in_sizes, int n_in,
                              void* d_out, int out_size)
{
    const float* f     = (const float*)d_in[0];
    const void*  idxp  = (const void*) d_in[1];
    const float* W1    = (const float*)d_in[2];
    const float* b1    = (const float*)d_in[3];
    const float* gamma = (const float*)d_in[4];
    const float* beta  = (const float*)d_in[5];
    const float* rmean = (const float*)d_in[6];
    const float* rvar  = (const float*)d_in[7];
    const float* Ws    = (const float*)d_in[8];
    const float* Wm    = (const float*)d_in[9];
    const float* bm    = (const float*)d_in[10];
    float* out = (float*)d_out;

    const int N = in_sizes[0] / CIN;

    static int attr_set = 0;
    if (!attr_set) {
        cudaFuncSetAttribute(kernelA_mma,
                             cudaFuncAttributeMaxDynamicSharedMemorySize, SMEM_TOTAL);
        attr_set = 1;
    }

    prep_kernel<<<32, 256>>>(W1, Ws, Wm, (const unsigned int*)idxp);
    kernelA_mma<<<(N + 63) / 64, 256, SMEM_TOTAL>>>(f, b1, gamma, beta, rmean, rvar, N);
    kernelB<<<(N + 7) / 8, 512>>>(idxp, bm, out, N);
}

// round 10
// speedup vs baseline: 1.3749x; 1.3749x over previous
#include <cuda_runtime.h>
#include <cuda_bf16.h>
#include <cuda_fp16.h>
#include <cstdint>

// Problem constants (fixed by the dataset)
#define NMAX 50000
#define CIN  128
#define C2   256
#define COUT 128
#define KNB  16

// Scratch (static device arrays; no allocation):
// g_eq[node]: 256 half = e = exp(z), then 256 half = q = e*y  (1KB per node)
__device__ __half g_eq[(size_t)NMAX * 512];
__device__ __nv_bfloat16 g_W1h[256 * 128];        // W1^T hi  [n][k]
__device__ __nv_bfloat16 g_W1l[256 * 128];        // W1^T lo
__device__ __nv_bfloat16 g_Wsh[256 * 256];        // Ws^T hi  [n][k]
__device__ __nv_bfloat16 g_Wsl[256 * 256];        // Ws^T lo
__device__ int g_idx64;

// ---------------------------------------------------------------------------
// mma.sync m16n8k16 bf16 (baseline PTX, valid on compute_103 virtual arch)
// ---------------------------------------------------------------------------
__device__ __forceinline__ void mma16816(float* d,
    uint32_t a0, uint32_t a1, uint32_t a2, uint32_t a3,
    uint32_t b0, uint32_t b1)
{
    asm volatile(
        "mma.sync.aligned.m16n8k16.row.col.f32.bf16.bf16.f32 "
        "{%0,%1,%2,%3}, {%4,%5,%6,%7}, {%8,%9}, {%0,%1,%2,%3};"
        : "+f"(d[0]), "+f"(d[1]), "+f"(d[2]), "+f"(d[3])
        : "r"(a0), "r"(a1), "r"(a2), "r"(a3), "r"(b0), "r"(b1));
}

// SMEM layout for kernelA (bytes). Strides 272/528 ≡ 4 mod 32 words.
#define XS   272
#define XH_OFF 0
#define XL_OFF 17408              // 64*272
#define YS   528
#define YSH_OFF 0
#define YSL_OFF 33792             // 64*528
#define WS   272
#define W_OFF 69632
#define WHL  69632                // 256*272
#define PAR_OFF 208896
#define SMEM_TOTAL 212992

// ---------------------------------------------------------------------------
// Prep: pack W1^T, Ws^T bf16 hi/lo, [n][k]; idx dtype detect. 96 blocks.
// ---------------------------------------------------------------------------
__global__ __launch_bounds__(256) void prep_kernel(
    const float* __restrict__ W1,
    const float* __restrict__ Ws,
    const unsigned int* __restrict__ idxraw)
{
    const int b = blockIdx.x, tid = threadIdx.x;
    if (b == 0 && tid == 0) {   // int64 -> every odd 32-bit word zero
        int is64 = 1;
        #pragma unroll 1
        for (int t = 1; t < 256; t += 2)
            if (idxraw[t] != 0u) { is64 = 0; break; }
        g_idx64 = is64;
    }
    if (b < 32) {                // W1: 32768 elems, 1024 per block
        #pragma unroll
        for (int i = 0; i < 4; i++) {
            int idx = b * 1024 + tid + i * 256;
            int k = idx >> 8, n = idx & 255;
            float v = W1[(size_t)k * 256 + n];
            __nv_bfloat16 hi = __float2bfloat16(v);
            g_W1h[n * 128 + k] = hi;
            g_W1l[n * 128 + k] = __float2bfloat16(v - __bfloat162float(hi));
        }
    } else {                     // Ws: 65536 elems, blocks 32..95
        #pragma unroll
        for (int i = 0; i < 4; i++) {
            int idx = (b - 32) * 1024 + tid + i * 256;
            int k = idx >> 8, n = idx & 255;
            float v = Ws[(size_t)k * 256 + n];
            __nv_bfloat16 hi = __float2bfloat16(v);
            g_Wsh[n * 256 + k] = hi;
            g_Wsl[n * 256 + k] = __float2bfloat16(v - __bfloat162float(hi));
        }
    }
}

// No-op kernels: steer ncu's "-s 5 -c 1" window onto kernelB
// (launch order: memset, prep, A, noop, noop, B -> #5 = kernelB).
__global__ void noop_kernel() {}

// ---------------------------------------------------------------------------
// kernelA_mma: block = 64 rows x 256 cols, 8 warps (4 M x 2 N).
// GEMM1 (X@W1, bf16 hi/lo 3-MMA) -> BN -> ys (smem) -> GEMM2 (ys@Ws)
// -> epilogue e=exp(z), q=e*y stored fp16 interleaved.  (R6, passing)
// ---------------------------------------------------------------------------
__global__ __launch_bounds__(256, 1) void kernelA_mma(
    const float* __restrict__ f,
    const float* __restrict__ b1, const float* __restrict__ gamma,
    const float* __restrict__ beta, const float* __restrict__ rmean,
    const float* __restrict__ rvar, int N)
{
    extern __shared__ unsigned char smem[];
    const int tid = threadIdx.x, wid = tid >> 5, lane = tid & 31;
    const int ms = wid & 3, nh = wid >> 2;
    const int g = lane >> 2, kt = lane & 3;
    const int row0 = blockIdx.x * 64;

    float* Pb  = (float*)(smem + PAR_OFF);
    float* Pinv = Pb + 256; float* Pmu = Pinv + 256; float* Pbt = Pmu + 256;
    {
        int c = tid;
        Pb[c]   = b1[c];
        Pinv[c] = gamma[c] * rsqrtf(rvar[c] + 1e-5f);
        Pmu[c]  = rmean[c];
        Pbt[c]  = beta[c];
    }

    // Stage X (64x128 f32 -> bf16 hi/lo)
    #pragma unroll
    for (int i = 0; i < 8; i++) {
        int fi = tid + i * 256;
        int r = fi >> 5, c4 = fi & 31;
        float4 v = make_float4(0.f, 0.f, 0.f, 0.f);
        if (row0 + r < N) v = ((const float4*)(f + (size_t)(row0 + r) * CIN))[c4];
        __nv_bfloat162 h0 = __floats2bfloat162_rn(v.x, v.y);
        __nv_bfloat162 h1 = __floats2bfloat162_rn(v.z, v.w);
        __nv_bfloat162 l0 = __floats2bfloat162_rn(v.x - __bfloat162float(h0.x),
                                                  v.y - __bfloat162float(h0.y));
        __nv_bfloat162 l1 = __floats2bfloat162_rn(v.z - __bfloat162float(h1.x),
                                                  v.w - __bfloat162float(h1.y));
        uint2 hu, lu;
        hu.x = *(uint32_t*)&h0; hu.y = *(uint32_t*)&h1;
        lu.x = *(uint32_t*)&l0; lu.y = *(uint32_t*)&l1;
        *(uint2*)(smem + XH_OFF + r * XS + c4 * 8) = hu;
        *(uint2*)(smem + XL_OFF + r * XS + c4 * 8) = lu;
    }
    // Stage W1
    #pragma unroll
    for (int i = 0; i < 32; i++) {
        int u = tid + i * 256;
        int half_ = u >> 12, r = (u >> 4) & 255, c = u & 15;
        const uint4* src = (const uint4*)(half_ ? (const void*)g_W1l : (const void*)g_W1h);
        *(uint4*)(smem + W_OFF + half_ * WHL + r * WS + c * 16) = src[r * 16 + c];
    }
    __syncthreads();

    float acc[16][4];
    #pragma unroll
    for (int t = 0; t < 16; t++)
        #pragma unroll
        for (int j = 0; j < 4; j++) acc[t][j] = 0.f;

    // GEMM 1: K = 128
    {
        const unsigned char* Ah = smem + XH_OFF + (16 * ms + g) * XS + kt * 4;
        const unsigned char* Al = smem + XL_OFF + (16 * ms + g) * XS + kt * 4;
        const unsigned char* Bb = smem + W_OFF + (nh * 128 + g) * WS + kt * 4;
        #pragma unroll 1
        for (int ks = 0; ks < 8; ks++) {
            const int kb = ks * 32;
            uint32_t ah0 = *(const uint32_t*)(Ah + kb);
            uint32_t ah1 = *(const uint32_t*)(Ah + kb + 8 * XS);
            uint32_t ah2 = *(const uint32_t*)(Ah + kb + 16);
            uint32_t ah3 = *(const uint32_t*)(Ah + kb + 8 * XS + 16);
            uint32_t al0 = *(const uint32_t*)(Al + kb);
            uint32_t al1 = *(const uint32_t*)(Al + kb + 8 * XS);
            uint32_t al2 = *(const uint32_t*)(Al + kb + 16);
            uint32_t al3 = *(const uint32_t*)(Al + kb + 8 * XS + 16);
            #pragma unroll
            for (int t = 0; t < 16; t++) {
                const unsigned char* Bp = Bb + t * 8 * WS + kb;
                uint32_t bh0 = *(const uint32_t*)(Bp);
                uint32_t bh1 = *(const uint32_t*)(Bp + 16);
                uint32_t bl0 = *(const uint32_t*)(Bp + WHL);
                uint32_t bl1 = *(const uint32_t*)(Bp + WHL + 16);
                mma16816(acc[t], ah0, ah1, ah2, ah3, bh0, bh1);
                mma16816(acc[t], ah0, ah1, ah2, ah3, bl0, bl1);
                mma16816(acc[t], al0, al1, al2, al3, bh0, bh1);
            }
        }
    }
    __syncthreads();

    // BN epilogue -> ys hi/lo (smem)
    #pragma unroll
    for (int t = 0; t < 16; t++) {
        const int nc0 = nh * 128 + t * 8 + 2 * kt;
        float2 pb  = *(const float2*)&Pb[nc0];
        float2 pin = *(const float2*)&Pinv[nc0];
        float2 pmu = *(const float2*)&Pmu[nc0];
        float2 pbt = *(const float2*)&Pbt[nc0];
        float y00 = (fmaxf(acc[t][0] + pb.x, 0.f) - pmu.x) * pin.x + pbt.x;
        float y01 = (fmaxf(acc[t][1] + pb.y, 0.f) - pmu.y) * pin.y + pbt.y;
        float y10 = (fmaxf(acc[t][2] + pb.x, 0.f) - pmu.x) * pin.x + pbt.x;
        float y11 = (fmaxf(acc[t][3] + pb.y, 0.f) - pmu.y) * pin.y + pbt.y;
        __nv_bfloat162 h0 = __floats2bfloat162_rn(y00, y01);
        __nv_bfloat162 h1 = __floats2bfloat162_rn(y10, y11);
        __nv_bfloat162 l0 = __floats2bfloat162_rn(y00 - __bfloat162float(h0.x),
                                                  y01 - __bfloat162float(h0.y));
        __nv_bfloat162 l1 = __floats2bfloat162_rn(y10 - __bfloat162float(h1.x),
                                                  y11 - __bfloat162float(h1.y));
        const int r0 = 16 * ms + g;
        *(uint32_t*)(smem + YSH_OFF + r0 * YS + nc0 * 2)       = *(uint32_t*)&h0;
        *(uint32_t*)(smem + YSH_OFF + (r0 + 8) * YS + nc0 * 2) = *(uint32_t*)&h1;
        *(uint32_t*)(smem + YSL_OFF + r0 * YS + nc0 * 2)       = *(uint32_t*)&l0;
        *(uint32_t*)(smem + YSL_OFF + (r0 + 8) * YS + nc0 * 2) = *(uint32_t*)&l1;
    }

    // GEMM 2: K = 256 in 2 staged chunks
    #pragma unroll
    for (int t = 0; t < 16; t++)
        #pragma unroll
        for (int j = 0; j < 4; j++) acc[t][j] = 0.f;

    #pragma unroll 1
    for (int chunk = 0; chunk < 2; chunk++) {
        __syncthreads();
        #pragma unroll
        for (int i = 0; i < 32; i++) {
            int u = tid + i * 256;
            int half_ = u >> 12, r = (u >> 4) & 255, c = u & 15;
            const unsigned char* src =
                (const unsigned char*)(half_ ? (const void*)g_Wsl : (const void*)g_Wsh)
                + (size_t)r * 512 + chunk * 256 + c * 16;
            *(uint4*)(smem + W_OFF + half_ * WHL + r * WS + c * 16) = *(const uint4*)src;
        }
        __syncthreads();

        const unsigned char* Ah = smem + YSH_OFF + (16 * ms + g) * YS + chunk * 256 + kt * 4;
        const unsigned char* Al = smem + YSL_OFF + (16 * ms + g) * YS + chunk * 256 + kt * 4;
        const unsigned char* Bb = smem + W_OFF + (nh * 128 + g) * WS + kt * 4;
        #pragma unroll 1
        for (int ks = 0; ks < 8; ks++) {
            const int kb = ks * 32;
            uint32_t ah0 = *(const uint32_t*)(Ah + kb);
            uint32_t ah1 = *(const uint32_t*)(Ah + kb + 8 * YS);
            uint32_t ah2 = *(const uint32_t*)(Ah + kb + 16);
            uint32_t ah3 = *(const uint32_t*)(Ah + kb + 8 * YS + 16);
            uint32_t al0 = *(const uint32_t*)(Al + kb);
            uint32_t al1 = *(const uint32_t*)(Al + kb + 8 * YS);
            uint32_t al2 = *(const uint32_t*)(Al + kb + 16);
            uint32_t al3 = *(const uint32_t*)(Al + kb + 8 * YS + 16);
            #pragma unroll
            for (int t = 0; t < 16; t++) {
                const unsigned char* Bp = Bb + t * 8 * WS + kb;
                uint32_t bh0 = *(const uint32_t*)(Bp);
                uint32_t bh1 = *(const uint32_t*)(Bp + 16);
                uint32_t bl0 = *(const uint32_t*)(Bp + WHL);
                uint32_t bl1 = *(const uint32_t*)(Bp + WHL + 16);
                mma16816(acc[t], ah0, ah1, ah2, ah3, bh0, bh1);
                mma16816(acc[t], ah0, ah1, ah2, ah3, bl0, bl1);
                mma16816(acc[t], al0, al1, al2, al3, bh0, bh1);
            }
        }
    }

    // Final epilogue: e = exp(z), q = e*y; fp16 interleaved stores
    #pragma unroll
    for (int t = 0; t < 16; t++) {
        const int nc0 = nh * 128 + t * 8 + 2 * kt;
        const int r0 = 16 * ms + g;
        uint32_t yh0 = *(const uint32_t*)(smem + YSH_OFF + r0 * YS + nc0 * 2);
        uint32_t yl0 = *(const uint32_t*)(smem + YSL_OFF + r0 * YS + nc0 * 2);
        uint32_t yh1 = *(const uint32_t*)(smem + YSH_OFF + (r0 + 8) * YS + nc0 * 2);
        uint32_t yl1 = *(const uint32_t*)(smem + YSL_OFF + (r0 + 8) * YS + nc0 * 2);
        __nv_bfloat162 h0 = *(__nv_bfloat162*)&yh0, l0 = *(__nv_bfloat162*)&yl0;
        __nv_bfloat162 h1 = *(__nv_bfloat162*)&yh1, l1 = *(__nv_bfloat162*)&yl1;
        float y00 = __bfloat162float(h0.x) + __bfloat162float(l0.x);
        float y01 = __bfloat162float(h0.y) + __bfloat162float(l0.y);
        float y10 = __bfloat162float(h1.x) + __bfloat162float(l1.x);
        float y11 = __bfloat162float(h1.y) + __bfloat162float(l1.y);
        float e00 = __expf(acc[t][0]), e01 = __expf(acc[t][1]);
        float e10 = __expf(acc[t][2]), e11 = __expf(acc[t][3]);
        int gr0 = row0 + r0, gr1 = gr0 + 8;
        if (gr0 < N) {
            *(__half2*)(g_eq + (size_t)gr0 * 512 + nc0)       = __floats2half2_rn(e00, e01);
            *(__half2*)(g_eq + (size_t)gr0 * 512 + 256 + nc0) = __floats2half2_rn(e00 * y00, e01 * y01);
        }
        if (gr1 < N) {
            *(__half2*)(g_eq + (size_t)gr1 * 512 + nc0)       = __floats2half2_rn(e10, e11);
            *(__half2*)(g_eq + (size_t)gr1 * 512 + 256 + nc0) = __floats2half2_rn(e10 * y10, e11 * y11);
        }
    }
}

// ---------------------------------------------------------------------------
// Kernel B (R6-exact, best known): block = 8 nodes, 256 threads.
// Phase 1: warp-per-node fp16 gather (2 LDG.128/neighbor), fp32 accumulate,
//          feat = num/den. Phase 2: block-cooperative out = feat @ Wm + bm.
// ---------------------------------------------------------------------------
__global__ __launch_bounds__(256) void kernelB(
    const void* __restrict__ idxp,
    const float* __restrict__ Wm,
    const float* __restrict__ bm,
    float* __restrict__ out,
    int N)
{
    __shared__ float feat[8][C2];

    const int wl   = threadIdx.x >> 5;
    const int lane = threadIdx.x & 31;
    const int n    = blockIdx.x * 8 + wl;
    const int ncl  = (n < N) ? n : (N - 1);

    const int is64 = g_idx64;

    int my = 0;
    if (lane < KNB) {
        if (is64) my = (int)((const long long*)idxp)[(size_t)ncl * KNB + lane];
        else      my = ((const int*)idxp)[(size_t)ncl * KNB + lane];
    }
    int nb[KNB];
    #pragma unroll
    for (int k = 0; k < KNB; k++)
        nb[k] = __shfl_sync(0xffffffffu, my, k);

    // Lane owns channels 8*lane .. 8*lane+7
    float den[8], num[8];
    #pragma unroll
    for (int q = 0; q < 8; q++) { den[q] = 0.f; num[q] = 0.f; }

    #pragma unroll 4
    for (int k = 0; k < KNB; k++) {
        const uint4* row = (const uint4*)(g_eq + (size_t)nb[k] * 512);
        uint4 ev = row[lane];        // e halves 8l..8l+7
        uint4 qv = row[32 + lane];   // q halves
        const __half2* eh = (const __half2*)&ev;
        const __half2* qh = (const __half2*)&qv;
        #pragma unroll
        for (int j = 0; j < 4; j++) {
            float2 fe = __half22float2(eh[j]);
            float2 fq = __half22float2(qh[j]);
            den[2*j]   += fe.x;  den[2*j+1] += fe.y;
            num[2*j]   += fq.x;  num[2*j+1] += fq.y;
        }
    }

    {
        float4 r0, r1;
        r0.x = num[0] / den[0]; r0.y = num[1] / den[1];
        r0.z = num[2] / den[2]; r0.w = num[3] / den[3];
        r1.x = num[4] / den[4]; r1.y = num[5] / den[5];
        r1.z = num[6] / den[6]; r1.w = num[7] / den[7];
        ((float4*)feat[wl])[2 * lane]     = r0;
        ((float4*)feat[wl])[2 * lane + 1] = r1;
    }
    __syncthreads();

    const int c = threadIdx.x & 127;
    const int h = threadIdx.x >> 7;
    float a0 = 0.f, a1 = 0.f, a2 = 0.f, a3 = 0.f;

    #pragma unroll 4
    for (int i = 0; i < C2; i += 4) {
        float4 f0 = *(const float4*)&feat[4*h + 0][i];
        float4 f1 = *(const float4*)&feat[4*h + 1][i];
        float4 f2 = *(const float4*)&feat[4*h + 2][i];
        float4 f3 = *(const float4*)&feat[4*h + 3][i];
        float w0 = Wm[(size_t)(i + 0) * COUT + c];
        float w1 = Wm[(size_t)(i + 1) * COUT + c];
        float w2 = Wm[(size_t)(i + 2) * COUT + c];
        float w3 = Wm[(size_t)(i + 3) * COUT + c];
        a0 = fmaf(f0.x, w0, a0); a0 = fmaf(f0.y, w1, a0);
        a0 = fmaf(f0.z, w2, a0); a0 = fmaf(f0.w, w3, a0);
        a1 = fmaf(f1.x, w0, a1); a1 = fmaf(f1.y, w1, a1);
        a1 = fmaf(f1.z, w2, a1); a1 = fmaf(f1.w, w3, a1);
        a2 = fmaf(f2.x, w0, a2); a2 = fmaf(f2.y, w1, a2);
        a2 = fmaf(f2.z, w2, a2); a2 = fmaf(f2.w, w3, a2);
        a3 = fmaf(f3.x, w0, a3); a3 = fmaf(f3.y, w1, a3);
        a3 = fmaf(f3.z, w2, a3); a3 = fmaf(f3.w, w3, a3);
    }

    const int nodebase = blockIdx.x * 8 + 4 * h;
    const float bb = bm[c];
    if (nodebase + 0 < N) out[(size_t)(nodebase + 0) * COUT + c] = a0 + bb;
    if (nodebase + 1 < N) out[(size_t)(nodebase + 1) * COUT + c] = a1 + bb;
    if (nodebase + 2 < N) out[(size_t)(nodebase + 2) * COUT + c] = a2 + bb;
    if (nodebase + 3 < N) out[(size_t)(nodebase + 3) * COUT + c] = a3 + bb;
}

// ---------------------------------------------------------------------------
// Launch
// ---------------------------------------------------------------------------
extern "C" void kernel_launch(void* const* d_in, const int* in_sizes, int n_in,
                              void* d_out, int out_size)
{
    const float* f     = (const float*)d_in[0];
    const void*  idxp  = (const void*) d_in[1];
    const float* W1    = (const float*)d_in[2];
    const float* b1    = (const float*)d_in[3];
    const float* gamma = (const float*)d_in[4];
    const float* beta  = (const float*)d_in[5];
    const float* rmean = (const float*)d_in[6];
    const float* rvar  = (const float*)d_in[7];
    const float* Ws    = (const float*)d_in[8];
    const float* Wm    = (const float*)d_in[9];
    const float* bm    = (const float*)d_in[10];
    float* out = (float*)d_out;

    const int N = in_sizes[0] / CIN;

    static int attr_set = 0;
    if (!attr_set) {
        cudaFuncSetAttribute(kernelA_mma,
                             cudaFuncAttributeMaxDynamicSharedMemorySize, SMEM_TOTAL);
        attr_set = 1;
    }

    prep_kernel<<<96, 256>>>(W1, Ws, (const unsigned int*)idxp);
    kernelA_mma<<<(N + 63) / 64, 256, SMEM_TOTAL>>>(f, b1, gamma, beta, rmean, rvar, N);
    noop_kernel<<<1, 32>>>();
    noop_kernel<<<1, 32>>>();
    kernelB<<<(N + 7) / 8, 256>>>(idxp, Wm, bm, out, N);
}

// round 11
// speedup vs baseline: 1.3850x; 1.0073x over previous
#include <cuda_runtime.h>
#include <cuda_bf16.h>
#include <cuda_fp16.h>
#include <cstdint>

// Problem constants (fixed by the dataset)
#define NMAX 50000
#define CIN  128
#define C2   256
#define COUT 128
#define KNB  16

// Scratch (static device arrays; no allocation):
// g_eq[node]: 256 half = e = exp(z), then 256 half = q = e*y  (1KB per node)
__device__ __half g_eq[(size_t)NMAX * 512];
__device__ __nv_bfloat16 g_W1h[256 * 128];        // W1^T hi  [n][k]
__device__ __nv_bfloat16 g_W1l[256 * 128];        // W1^T lo
__device__ __nv_bfloat16 g_Wsh[256 * 256];        // Ws^T hi  [n][k]
__device__ __nv_bfloat16 g_Wsl[256 * 256];        // Ws^T lo
__device__ int g_idx64;

// ---------------------------------------------------------------------------
// mma.sync m16n8k16 bf16 (baseline PTX, valid on compute_103 virtual arch)
// ---------------------------------------------------------------------------
__device__ __forceinline__ void mma16816(float* d,
    uint32_t a0, uint32_t a1, uint32_t a2, uint32_t a3,
    uint32_t b0, uint32_t b1)
{
    asm volatile(
        "mma.sync.aligned.m16n8k16.row.col.f32.bf16.bf16.f32 "
        "{%0,%1,%2,%3}, {%4,%5,%6,%7}, {%8,%9}, {%0,%1,%2,%3};"
        : "+f"(d[0]), "+f"(d[1]), "+f"(d[2]), "+f"(d[3])
        : "r"(a0), "r"(a1), "r"(a2), "r"(a3), "r"(b0), "r"(b1));
}

// SMEM layout for kernelA (bytes). Strides 272/528 ≡ 4 mod 32 words.
#define XS   272
#define XH_OFF 0
#define XL_OFF 17408              // 64*272
#define YS   528
#define YSH_OFF 0
#define YSL_OFF 33792             // 64*528
#define WS   272
#define W_OFF 69632
#define WHL  69632                // 256*272
#define PAR_OFF 208896
#define SMEM_TOTAL 212992

// ---------------------------------------------------------------------------
// Prep: pack W1^T, Ws^T bf16 hi/lo, [n][k]; idx dtype detect. 96 blocks.
// ---------------------------------------------------------------------------
__global__ __launch_bounds__(256) void prep_kernel(
    const float* __restrict__ W1,
    const float* __restrict__ Ws,
    const unsigned int* __restrict__ idxraw)
{
    const int b = blockIdx.x, tid = threadIdx.x;
    if (b == 0 && tid == 0) {   // int64 -> every odd 32-bit word zero
        int is64 = 1;
        #pragma unroll 1
        for (int t = 1; t < 256; t += 2)
            if (idxraw[t] != 0u) { is64 = 0; break; }
        g_idx64 = is64;
    }
    if (b < 32) {                // W1: 32768 elems, 1024 per block
        #pragma unroll
        for (int i = 0; i < 4; i++) {
            int idx = b * 1024 + tid + i * 256;
            int k = idx >> 8, n = idx & 255;
            float v = W1[(size_t)k * 256 + n];
            __nv_bfloat16 hi = __float2bfloat16(v);
            g_W1h[n * 128 + k] = hi;
            g_W1l[n * 128 + k] = __float2bfloat16(v - __bfloat162float(hi));
        }
    } else {                     // Ws: 65536 elems, blocks 32..95
        #pragma unroll
        for (int i = 0; i < 4; i++) {
            int idx = (b - 32) * 1024 + tid + i * 256;
            int k = idx >> 8, n = idx & 255;
            float v = Ws[(size_t)k * 256 + n];
            __nv_bfloat16 hi = __float2bfloat16(v);
            g_Wsh[n * 256 + k] = hi;
            g_Wsl[n * 256 + k] = __float2bfloat16(v - __bfloat162float(hi));
        }
    }
}

// One no-op: makes kernelB the 5th launch overall (memset, prep, A, noop, B)
// so ncu's "-s 5 -c 1" window captures kernelB.
__global__ void noop_kernel() {}

// ---------------------------------------------------------------------------
// kernelA_mma: block = 64 rows x 256 cols, 8 warps (4 M x 2 N).
// GEMM1 (X@W1, bf16 hi/lo 3-MMA) -> BN -> ys (smem) -> GEMM2 (ys@Ws)
// -> epilogue e=exp(z), q=e*y stored fp16 interleaved.  (best known)
// ---------------------------------------------------------------------------
__global__ __launch_bounds__(256, 1) void kernelA_mma(
    const float* __restrict__ f,
    const float* __restrict__ b1, const float* __restrict__ gamma,
    const float* __restrict__ beta, const float* __restrict__ rmean,
    const float* __restrict__ rvar, int N)
{
    extern __shared__ unsigned char smem[];
    const int tid = threadIdx.x, wid = tid >> 5, lane = tid & 31;
    const int ms = wid & 3, nh = wid >> 2;
    const int g = lane >> 2, kt = lane & 3;
    const int row0 = blockIdx.x * 64;

    float* Pb  = (float*)(smem + PAR_OFF);
    float* Pinv = Pb + 256; float* Pmu = Pinv + 256; float* Pbt = Pmu + 256;
    {
        int c = tid;
        Pb[c]   = b1[c];
        Pinv[c] = gamma[c] * rsqrtf(rvar[c] + 1e-5f);
        Pmu[c]  = rmean[c];
        Pbt[c]  = beta[c];
    }

    // Stage X (64x128 f32 -> bf16 hi/lo)
    #pragma unroll
    for (int i = 0; i < 8; i++) {
        int fi = tid + i * 256;
        int r = fi >> 5, c4 = fi & 31;
        float4 v = make_float4(0.f, 0.f, 0.f, 0.f);
        if (row0 + r < N) v = ((const float4*)(f + (size_t)(row0 + r) * CIN))[c4];
        __nv_bfloat162 h0 = __floats2bfloat162_rn(v.x, v.y);
        __nv_bfloat162 h1 = __floats2bfloat162_rn(v.z, v.w);
        __nv_bfloat162 l0 = __floats2bfloat162_rn(v.x - __bfloat162float(h0.x),
                                                  v.y - __bfloat162float(h0.y));
        __nv_bfloat162 l1 = __floats2bfloat162_rn(v.z - __bfloat162float(h1.x),
                                                  v.w - __bfloat162float(h1.y));
        uint2 hu, lu;
        hu.x = *(uint32_t*)&h0; hu.y = *(uint32_t*)&h1;
        lu.x = *(uint32_t*)&l0; lu.y = *(uint32_t*)&l1;
        *(uint2*)(smem + XH_OFF + r * XS + c4 * 8) = hu;
        *(uint2*)(smem + XL_OFF + r * XS + c4 * 8) = lu;
    }
    // Stage W1
    #pragma unroll
    for (int i = 0; i < 32; i++) {
        int u = tid + i * 256;
        int half_ = u >> 12, r = (u >> 4) & 255, c = u & 15;
        const uint4* src = (const uint4*)(half_ ? (const void*)g_W1l : (const void*)g_W1h);
        *(uint4*)(smem + W_OFF + half_ * WHL + r * WS + c * 16) = src[r * 16 + c];
    }
    __syncthreads();

    float acc[16][4];
    #pragma unroll
    for (int t = 0; t < 16; t++)
        #pragma unroll
        for (int j = 0; j < 4; j++) acc[t][j] = 0.f;

    // GEMM 1: K = 128
    {
        const unsigned char* Ah = smem + XH_OFF + (16 * ms + g) * XS + kt * 4;
        const unsigned char* Al = smem + XL_OFF + (16 * ms + g) * XS + kt * 4;
        const unsigned char* Bb = smem + W_OFF + (nh * 128 + g) * WS + kt * 4;
        #pragma unroll 1
        for (int ks = 0; ks < 8; ks++) {
            const int kb = ks * 32;
            uint32_t ah0 = *(const uint32_t*)(Ah + kb);
            uint32_t ah1 = *(const uint32_t*)(Ah + kb + 8 * XS);
            uint32_t ah2 = *(const uint32_t*)(Ah + kb + 16);
            uint32_t ah3 = *(const uint32_t*)(Ah + kb + 8 * XS + 16);
            uint32_t al0 = *(const uint32_t*)(Al + kb);
            uint32_t al1 = *(const uint32_t*)(Al + kb + 8 * XS);
            uint32_t al2 = *(const uint32_t*)(Al + kb + 16);
            uint32_t al3 = *(const uint32_t*)(Al + kb + 8 * XS + 16);
            #pragma unroll
            for (int t = 0; t < 16; t++) {
                const unsigned char* Bp = Bb + t * 8 * WS + kb;
                uint32_t bh0 = *(const uint32_t*)(Bp);
                uint32_t bh1 = *(const uint32_t*)(Bp + 16);
                uint32_t bl0 = *(const uint32_t*)(Bp + WHL);
                uint32_t bl1 = *(const uint32_t*)(Bp + WHL + 16);
                mma16816(acc[t], ah0, ah1, ah2, ah3, bh0, bh1);
                mma16816(acc[t], ah0, ah1, ah2, ah3, bl0, bl1);
                mma16816(acc[t], al0, al1, al2, al3, bh0, bh1);
            }
        }
    }
    __syncthreads();

    // BN epilogue -> ys hi/lo (smem)
    #pragma unroll
    for (int t = 0; t < 16; t++) {
        const int nc0 = nh * 128 + t * 8 + 2 * kt;
        float2 pb  = *(const float2*)&Pb[nc0];
        float2 pin = *(const float2*)&Pinv[nc0];
        float2 pmu = *(const float2*)&Pmu[nc0];
        float2 pbt = *(const float2*)&Pbt[nc0];
        float y00 = (fmaxf(acc[t][0] + pb.x, 0.f) - pmu.x) * pin.x + pbt.x;
        float y01 = (fmaxf(acc[t][1] + pb.y, 0.f) - pmu.y) * pin.y + pbt.y;
        float y10 = (fmaxf(acc[t][2] + pb.x, 0.f) - pmu.x) * pin.x + pbt.x;
        float y11 = (fmaxf(acc[t][3] + pb.y, 0.f) - pmu.y) * pin.y + pbt.y;
        __nv_bfloat162 h0 = __floats2bfloat162_rn(y00, y01);
        __nv_bfloat162 h1 = __floats2bfloat162_rn(y10, y11);
        __nv_bfloat162 l0 = __floats2bfloat162_rn(y00 - __bfloat162float(h0.x),
                                                  y01 - __bfloat162float(h0.y));
        __nv_bfloat162 l1 = __floats2bfloat162_rn(y10 - __bfloat162float(h1.x),
                                                  y11 - __bfloat162float(h1.y));
        const int r0 = 16 * ms + g;
        *(uint32_t*)(smem + YSH_OFF + r0 * YS + nc0 * 2)       = *(uint32_t*)&h0;
        *(uint32_t*)(smem + YSH_OFF + (r0 + 8) * YS + nc0 * 2) = *(uint32_t*)&h1;
        *(uint32_t*)(smem + YSL_OFF + r0 * YS + nc0 * 2)       = *(uint32_t*)&l0;
        *(uint32_t*)(smem + YSL_OFF + (r0 + 8) * YS + nc0 * 2) = *(uint32_t*)&l1;
    }

    // GEMM 2: K = 256 in 2 staged chunks
    #pragma unroll
    for (int t = 0; t < 16; t++)
        #pragma unroll
        for (int j = 0; j < 4; j++) acc[t][j] = 0.f;

    #pragma unroll 1
    for (int chunk = 0; chunk < 2; chunk++) {
        __syncthreads();
        #pragma unroll
        for (int i = 0; i < 32; i++) {
            int u = tid + i * 256;
            int half_ = u >> 12, r = (u >> 4) & 255, c = u & 15;
            const unsigned char* src =
                (const unsigned char*)(half_ ? (const void*)g_Wsl : (const void*)g_Wsh)
                + (size_t)r * 512 + chunk * 256 + c * 16;
            *(uint4*)(smem + W_OFF + half_ * WHL + r * WS + c * 16) = *(const uint4*)src;
        }
        __syncthreads();

        const unsigned char* Ah = smem + YSH_OFF + (16 * ms + g) * YS + chunk * 256 + kt * 4;
        const unsigned char* Al = smem + YSL_OFF + (16 * ms + g) * YS + chunk * 256 + kt * 4;
        const unsigned char* Bb = smem + W_OFF + (nh * 128 + g) * WS + kt * 4;
        #pragma unroll 1
        for (int ks = 0; ks < 8; ks++) {
            const int kb = ks * 32;
            uint32_t ah0 = *(const uint32_t*)(Ah + kb);
            uint32_t ah1 = *(const uint32_t*)(Ah + kb + 8 * YS);
            uint32_t ah2 = *(const uint32_t*)(Ah + kb + 16);
            uint32_t ah3 = *(const uint32_t*)(Ah + kb + 8 * YS + 16);
            uint32_t al0 = *(const uint32_t*)(Al + kb);
            uint32_t al1 = *(const uint32_t*)(Al + kb + 8 * YS);
            uint32_t al2 = *(const uint32_t*)(Al + kb + 16);
            uint32_t al3 = *(const uint32_t*)(Al + kb + 8 * YS + 16);
            #pragma unroll
            for (int t = 0; t < 16; t++) {
                const unsigned char* Bp = Bb + t * 8 * WS + kb;
                uint32_t bh0 = *(const uint32_t*)(Bp);
                uint32_t bh1 = *(const uint32_t*)(Bp + 16);
                uint32_t bl0 = *(const uint32_t*)(Bp + WHL);
                uint32_t bl1 = *(const uint32_t*)(Bp + WHL + 16);
                mma16816(acc[t], ah0, ah1, ah2, ah3, bh0, bh1);
                mma16816(acc[t], ah0, ah1, ah2, ah3, bl0, bl1);
                mma16816(acc[t], al0, al1, al2, al3, bh0, bh1);
            }
        }
    }

    // Final epilogue: e = exp(z), q = e*y; fp16 interleaved stores
    #pragma unroll
    for (int t = 0; t < 16; t++) {
        const int nc0 = nh * 128 + t * 8 + 2 * kt;
        const int r0 = 16 * ms + g;
        uint32_t yh0 = *(const uint32_t*)(smem + YSH_OFF + r0 * YS + nc0 * 2);
        uint32_t yl0 = *(const uint32_t*)(smem + YSL_OFF + r0 * YS + nc0 * 2);
        uint32_t yh1 = *(const uint32_t*)(smem + YSH_OFF + (r0 + 8) * YS + nc0 * 2);
        uint32_t yl1 = *(const uint32_t*)(smem + YSL_OFF + (r0 + 8) * YS + nc0 * 2);
        __nv_bfloat162 h0 = *(__nv_bfloat162*)&yh0, l0 = *(__nv_bfloat162*)&yl0;
        __nv_bfloat162 h1 = *(__nv_bfloat162*)&yh1, l1 = *(__nv_bfloat162*)&yl1;
        float y00 = __bfloat162float(h0.x) + __bfloat162float(l0.x);
        float y01 = __bfloat162float(h0.y) + __bfloat162float(l0.y);
        float y10 = __bfloat162float(h1.x) + __bfloat162float(l1.x);
        float y11 = __bfloat162float(h1.y) + __bfloat162float(l1.y);
        float e00 = __expf(acc[t][0]), e01 = __expf(acc[t][1]);
        float e10 = __expf(acc[t][2]), e11 = __expf(acc[t][3]);
        int gr0 = row0 + r0, gr1 = gr0 + 8;
        if (gr0 < N) {
            *(__half2*)(g_eq + (size_t)gr0 * 512 + nc0)       = __floats2half2_rn(e00, e01);
            *(__half2*)(g_eq + (size_t)gr0 * 512 + 256 + nc0) = __floats2half2_rn(e00 * y00, e01 * y01);
        }
        if (gr1 < N) {
            *(__half2*)(g_eq + (size_t)gr1 * 512 + nc0)       = __floats2half2_rn(e10, e11);
            *(__half2*)(g_eq + (size_t)gr1 * 512 + 256 + nc0) = __floats2half2_rn(e10 * y10, e11 * y11);
        }
    }
}

// ---------------------------------------------------------------------------
// Kernel B (best known): block = 8 nodes, 256 threads.
// Phase 1: warp-per-node fp16 gather (2 LDG.128/neighbor), fp32 accumulate,
//          feat = num/den. Phase 2: block-cooperative out = feat @ Wm + bm.
// ---------------------------------------------------------------------------
__global__ __launch_bounds__(256) void kernelB(
    const void* __restrict__ idxp,
    const float* __restrict__ Wm,
    const float* __restrict__ bm,
    float* __restrict__ out,
    int N)
{
    __shared__ float feat[8][C2];

    const int wl   = threadIdx.x >> 5;
    const int lane = threadIdx.x & 31;
    const int n    = blockIdx.x * 8 + wl;
    const int ncl  = (n < N) ? n : (N - 1);

    const int is64 = g_idx64;

    int my = 0;
    if (lane < KNB) {
        if (is64) my = (int)((const long long*)idxp)[(size_t)ncl * KNB + lane];
        else      my = ((const int*)idxp)[(size_t)ncl * KNB + lane];
    }
    int nb[KNB];
    #pragma unroll
    for (int k = 0; k < KNB; k++)
        nb[k] = __shfl_sync(0xffffffffu, my, k);

    // Lane owns channels 8*lane .. 8*lane+7
    float den[8], num[8];
    #pragma unroll
    for (int q = 0; q < 8; q++) { den[q] = 0.f; num[q] = 0.f; }

    #pragma unroll 4
    for (int k = 0; k < KNB; k++) {
        const uint4* row = (const uint4*)(g_eq + (size_t)nb[k] * 512);
        uint4 ev = row[lane];        // e halves 8l..8l+7
        uint4 qv = row[32 + lane];   // q halves
        const __half2* eh = (const __half2*)&ev;
        const __half2* qh = (const __half2*)&qv;
        #pragma unroll
        for (int j = 0; j < 4; j++) {
            float2 fe = __half22float2(eh[j]);
            float2 fq = __half22float2(qh[j]);
            den[2*j]   += fe.x;  den[2*j+1] += fe.y;
            num[2*j]   += fq.x;  num[2*j+1] += fq.y;
        }
    }

    {
        float4 r0, r1;
        r0.x = num[0] / den[0]; r0.y = num[1] / den[1];
        r0.z = num[2] / den[2]; r0.w = num[3] / den[3];
        r1.x = num[4] / den[4]; r1.y = num[5] / den[5];
        r1.z = num[6] / den[6]; r1.w = num[7] / den[7];
        ((float4*)feat[wl])[2 * lane]     = r0;
        ((float4*)feat[wl])[2 * lane + 1] = r1;
    }
    __syncthreads();

    const int c = threadIdx.x & 127;
    const int h = threadIdx.x >> 7;
    float a0 = 0.f, a1 = 0.f, a2 = 0.f, a3 = 0.f;

    #pragma unroll 4
    for (int i = 0; i < C2; i += 4) {
        float4 f0 = *(const float4*)&feat[4*h + 0][i];
        float4 f1 = *(const float4*)&feat[4*h + 1][i];
        float4 f2 = *(const float4*)&feat[4*h + 2][i];
        float4 f3 = *(const float4*)&feat[4*h + 3][i];
        float w0 = Wm[(size_t)(i + 0) * COUT + c];
        float w1 = Wm[(size_t)(i + 1) * COUT + c];
        float w2 = Wm[(size_t)(i + 2) * COUT + c];
        float w3 = Wm[(size_t)(i + 3) * COUT + c];
        a0 = fmaf(f0.x, w0, a0); a0 = fmaf(f0.y, w1, a0);
        a0 = fmaf(f0.z, w2, a0); a0 = fmaf(f0.w, w3, a0);
        a1 = fmaf(f1.x, w0, a1); a1 = fmaf(f1.y, w1, a1);
        a1 = fmaf(f1.z, w2, a1); a1 = fmaf(f1.w, w3, a1);
        a2 = fmaf(f2.x, w0, a2); a2 = fmaf(f2.y, w1, a2);
        a2 = fmaf(f2.z, w2, a2); a2 = fmaf(f2.w, w3, a2);
        a3 = fmaf(f3.x, w0, a3); a3 = fmaf(f3.y, w1, a3);
        a3 = fmaf(f3.z, w2, a3); a3 = fmaf(f3.w, w3, a3);
    }

    const int nodebase = blockIdx.x * 8 + 4 * h;
    const float bb = bm[c];
    if (nodebase + 0 < N) out[(size_t)(nodebase + 0) * COUT + c] = a0 + bb;
    if (nodebase + 1 < N) out[(size_t)(nodebase + 1) * COUT + c] = a1 + bb;
    if (nodebase + 2 < N) out[(size_t)(nodebase + 2) * COUT + c] = a2 + bb;
    if (nodebase + 3 < N) out[(size_t)(nodebase + 3) * COUT + c] = a3 + bb;
}

// ---------------------------------------------------------------------------
// Launch
// ---------------------------------------------------------------------------
extern "C" void kernel_launch(void* const* d_in, const int* in_sizes, int n_in,
                              void* d_out, int out_size)
{
    const float* f     = (const float*)d_in[0];
    const void*  idxp  = (const void*) d_in[1];
    const float* W1    = (const float*)d_in[2];
    const float* b1    = (const float*)d_in[3];
    const float* gamma = (const float*)d_in[4];
    const float* beta  = (const float*)d_in[5];
    const float* rmean = (const float*)d_in[6];
    const float* rvar  = (const float*)d_in[7];
    const float* Ws    = (const float*)d_in[8];
    const float* Wm    = (const float*)d_in[9];
    const float* bm    = (const float*)d_in[10];
    float* out = (float*)d_out;

    const int N = in_sizes[0] / CIN;

    static int attr_set = 0;
    if (!attr_set) {
        cudaFuncSetAttribute(kernelA_mma,
                             cudaFuncAttributeMaxDynamicSharedMemorySize, SMEM_TOTAL);
        attr_set = 1;
    }

    prep_kernel<<<96, 256>>>(W1, Ws, (const unsigned int*)idxp);
    kernelA_mma<<<(N + 63) / 64, 256, SMEM_TOTAL>>>(f, b1, gamma, beta, rmean, rvar, N);
    noop_kernel<<<1, 32>>>();
    kernelB<<<(N + 7) / 8, 256>>>(idxp, Wm, bm, out, N);
}

// round 13
// speedup vs baseline: 1.7907x; 1.2929x over previous
#include <cuda_runtime.h>
#include <cuda_bf16.h>
#include <cuda_fp16.h>
#include <cstdint>

// Problem constants (fixed by the dataset)
#define NMAX 50000
#define CIN  128
#define C2   256
#define COUT 128
#define KNB  16

// Scratch (static device arrays; no allocation):
__device__ __half g_eq[(size_t)NMAX * 512];       // [node]: 256 e | 256 q (fp16)
__device__ __nv_bfloat16 g_fh[(size_t)NMAX * 256]; // feat hi (bf16)
__device__ __nv_bfloat16 g_fl[(size_t)NMAX * 256]; // feat lo
__device__ __nv_bfloat16 g_W1h[256 * 128];        // W1^T hi  [n][k]
__device__ __nv_bfloat16 g_W1l[256 * 128];
__device__ __nv_bfloat16 g_Wsh[256 * 256];        // Ws^T hi  [n][k]
__device__ __nv_bfloat16 g_Wsl[256 * 256];
__device__ __nv_bfloat16 g_Wmh[128 * 256];        // Wm^T hi  [n][k]
__device__ __nv_bfloat16 g_Wml[128 * 256];
__device__ int g_idx64;

// ---------------------------------------------------------------------------
// mma.sync m16n8k16 bf16 (baseline PTX, valid on compute_103 virtual arch)
// ---------------------------------------------------------------------------
__device__ __forceinline__ void mma16816(float* d,
    uint32_t a0, uint32_t a1, uint32_t a2, uint32_t a3,
    uint32_t b0, uint32_t b1)
{
    asm volatile(
        "mma.sync.aligned.m16n8k16.row.col.f32.bf16.bf16.f32 "
        "{%0,%1,%2,%3}, {%4,%5,%6,%7}, {%8,%9}, {%0,%1,%2,%3};"
        : "+f"(d[0]), "+f"(d[1]), "+f"(d[2]), "+f"(d[3])
        : "r"(a0), "r"(a1), "r"(a2), "r"(a3), "r"(b0), "r"(b1));
}

// SMEM layout for kernelA (bytes). Strides 272/528 ≡ 4 mod 32 words.
#define XS   272
#define XH_OFF 0
#define XL_OFF 17408              // 64*272
#define YS   528
#define YSH_OFF 0
#define YSL_OFF 33792             // 64*528
#define WS   272
#define W_OFF 69632
#define WHL  69632                // 256*272
#define PAR_OFF 208896
#define SMEM_TOTAL 212992

// SMEM layout for kernelC
#define C_FH  0                   // feat hi: 64*528 = 33792
#define C_FL  33792               // feat lo
#define C_WH  67584               // Wm chunk hi: 128*272 = 34816
#define C_WL  102400              // Wm chunk lo
#define C_SMEM 137216

// ---------------------------------------------------------------------------
// Prep: pack W1^T, Ws^T, Wm^T bf16 hi/lo, [n][k]; idx dtype detect. 128 blks.
// ---------------------------------------------------------------------------
__global__ __launch_bounds__(256) void prep_kernel(
    const float* __restrict__ W1,
    const float* __restrict__ Ws,
    const float* __restrict__ Wm,
    const unsigned int* __restrict__ idxraw)
{
    const int b = blockIdx.x, tid = threadIdx.x;
    if (b == 0 && tid == 0) {   // int64 -> every odd 32-bit word zero
        int is64 = 1;
        #pragma unroll 1
        for (int t = 1; t < 256; t += 2)
            if (idxraw[t] != 0u) { is64 = 0; break; }
        g_idx64 = is64;
    }
    if (b < 32) {                // W1: 32768 elems, 1024 per block
        #pragma unroll
        for (int i = 0; i < 4; i++) {
            int idx = b * 1024 + tid + i * 256;
            int k = idx >> 8, n = idx & 255;
            float v = W1[(size_t)k * 256 + n];
            __nv_bfloat16 hi = __float2bfloat16(v);
            g_W1h[n * 128 + k] = hi;
            g_W1l[n * 128 + k] = __float2bfloat16(v - __bfloat162float(hi));
        }
    } else if (b < 96) {         // Ws: 65536 elems, blocks 32..95
        #pragma unroll
        for (int i = 0; i < 4; i++) {
            int idx = (b - 32) * 1024 + tid + i * 256;
            int k = idx >> 8, n = idx & 255;
            float v = Ws[(size_t)k * 256 + n];
            __nv_bfloat16 hi = __float2bfloat16(v);
            g_Wsh[n * 256 + k] = hi;
            g_Wsl[n * 256 + k] = __float2bfloat16(v - __bfloat162float(hi));
        }
    } else {                     // Wm: 32768 elems (256k x 128n), blocks 96..127
        #pragma unroll
        for (int i = 0; i < 4; i++) {
            int idx = (b - 96) * 1024 + tid + i * 256;
            int k = idx >> 7, n = idx & 127;
            float v = Wm[(size_t)k * 128 + n];
            __nv_bfloat16 hi = __float2bfloat16(v);
            g_Wmh[n * 256 + k] = hi;
            g_Wml[n * 256 + k] = __float2bfloat16(v - __bfloat162float(hi));
        }
    }
}

// ---------------------------------------------------------------------------
// kernelA_mma (unchanged, best known): block = 64 rows x 256 cols, 8 warps.
// GEMM1 (X@W1, bf16 hi/lo 3-MMA) -> BN -> ys (smem) -> GEMM2 (ys@Ws)
// -> epilogue e=exp(z), q=e*y stored fp16 interleaved.
// ---------------------------------------------------------------------------
__global__ __launch_bounds__(256, 1) void kernelA_mma(
    const float* __restrict__ f,
    const float* __restrict__ b1, const float* __restrict__ gamma,
    const float* __restrict__ beta, const float* __restrict__ rmean,
    const float* __restrict__ rvar, int N)
{
    extern __shared__ unsigned char smem[];
    const int tid = threadIdx.x, wid = tid >> 5, lane = tid & 31;
    const int ms = wid & 3, nh = wid >> 2;
    const int g = lane >> 2, kt = lane & 3;
    const int row0 = blockIdx.x * 64;

    float* Pb  = (float*)(smem + PAR_OFF);
    float* Pinv = Pb + 256; float* Pmu = Pinv + 256; float* Pbt = Pmu + 256;
    {
        int c = tid;
        Pb[c]   = b1[c];
        Pinv[c] = gamma[c] * rsqrtf(rvar[c] + 1e-5f);
        Pmu[c]  = rmean[c];
        Pbt[c]  = beta[c];
    }

    // Stage X (64x128 f32 -> bf16 hi/lo)
    #pragma unroll
    for (int i = 0; i < 8; i++) {
        int fi = tid + i * 256;
        int r = fi >> 5, c4 = fi & 31;
        float4 v = make_float4(0.f, 0.f, 0.f, 0.f);
        if (row0 + r < N) v = ((const float4*)(f + (size_t)(row0 + r) * CIN))[c4];
        __nv_bfloat162 h0 = __floats2bfloat162_rn(v.x, v.y);
        __nv_bfloat162 h1 = __floats2bfloat162_rn(v.z, v.w);
        __nv_bfloat162 l0 = __floats2bfloat162_rn(v.x - __bfloat162float(h0.x),
                                                  v.y - __bfloat162float(h0.y));
        __nv_bfloat162 l1 = __floats2bfloat162_rn(v.z - __bfloat162float(h1.x),
                                                  v.w - __bfloat162float(h1.y));
        uint2 hu, lu;
        hu.x = *(uint32_t*)&h0; hu.y = *(uint32_t*)&h1;
        lu.x = *(uint32_t*)&l0; lu.y = *(uint32_t*)&l1;
        *(uint2*)(smem + XH_OFF + r * XS + c4 * 8) = hu;
        *(uint2*)(smem + XL_OFF + r * XS + c4 * 8) = lu;
    }
    // Stage W1
    #pragma unroll
    for (int i = 0; i < 32; i++) {
        int u = tid + i * 256;
        int half_ = u >> 12, r = (u >> 4) & 255, c = u & 15;
        const uint4* src = (const uint4*)(half_ ? (const void*)g_W1l : (const void*)g_W1h);
        *(uint4*)(smem + W_OFF + half_ * WHL + r * WS + c * 16) = src[r * 16 + c];
    }
    __syncthreads();

    float acc[16][4];
    #pragma unroll
    for (int t = 0; t < 16; t++)
        #pragma unroll
        for (int j = 0; j < 4; j++) acc[t][j] = 0.f;

    // GEMM 1: K = 128
    {
        const unsigned char* Ah = smem + XH_OFF + (16 * ms + g) * XS + kt * 4;
        const unsigned char* Al = smem + XL_OFF + (16 * ms + g) * XS + kt * 4;
        const unsigned char* Bb = smem + W_OFF + (nh * 128 + g) * WS + kt * 4;
        #pragma unroll 1
        for (int ks = 0; ks < 8; ks++) {
            const int kb = ks * 32;
            uint32_t ah0 = *(const uint32_t*)(Ah + kb);
            uint32_t ah1 = *(const uint32_t*)(Ah + kb + 8 * XS);
            uint32_t ah2 = *(const uint32_t*)(Ah + kb + 16);
            uint32_t ah3 = *(const uint32_t*)(Ah + kb + 8 * XS + 16);
            uint32_t al0 = *(const uint32_t*)(Al + kb);
            uint32_t al1 = *(const uint32_t*)(Al + kb + 8 * XS);
            uint32_t al2 = *(const uint32_t*)(Al + kb + 16);
            uint32_t al3 = *(const uint32_t*)(Al + kb + 8 * XS + 16);
            #pragma unroll
            for (int t = 0; t < 16; t++) {
                const unsigned char* Bp = Bb + t * 8 * WS + kb;
                uint32_t bh0 = *(const uint32_t*)(Bp);
                uint32_t bh1 = *(const uint32_t*)(Bp + 16);
                uint32_t bl0 = *(const uint32_t*)(Bp + WHL);
                uint32_t bl1 = *(const uint32_t*)(Bp + WHL + 16);
                mma16816(acc[t], ah0, ah1, ah2, ah3, bh0, bh1);
                mma16816(acc[t], ah0, ah1, ah2, ah3, bl0, bl1);
                mma16816(acc[t], al0, al1, al2, al3, bh0, bh1);
            }
        }
    }
    __syncthreads();

    // BN epilogue -> ys hi/lo (smem)
    #pragma unroll
    for (int t = 0; t < 16; t++) {
        const int nc0 = nh * 128 + t * 8 + 2 * kt;
        float2 pb  = *(const float2*)&Pb[nc0];
        float2 pin = *(const float2*)&Pinv[nc0];
        float2 pmu = *(const float2*)&Pmu[nc0];
        float2 pbt = *(const float2*)&Pbt[nc0];
        float y00 = (fmaxf(acc[t][0] + pb.x, 0.f) - pmu.x) * pin.x + pbt.x;
        float y01 = (fmaxf(acc[t][1] + pb.y, 0.f) - pmu.y) * pin.y + pbt.y;
        float y10 = (fmaxf(acc[t][2] + pb.x, 0.f) - pmu.x) * pin.x + pbt.x;
        float y11 = (fmaxf(acc[t][3] + pb.y, 0.f) - pmu.y) * pin.y + pbt.y;
        __nv_bfloat162 h0 = __floats2bfloat162_rn(y00, y01);
        __nv_bfloat162 h1 = __floats2bfloat162_rn(y10, y11);
        __nv_bfloat162 l0 = __floats2bfloat162_rn(y00 - __bfloat162float(h0.x),
                                                  y01 - __bfloat162float(h0.y));
        __nv_bfloat162 l1 = __floats2bfloat162_rn(y10 - __bfloat162float(h1.x),
                                                  y11 - __bfloat162float(h1.y));
        const int r0 = 16 * ms + g;
        *(uint32_t*)(smem + YSH_OFF + r0 * YS + nc0 * 2)       = *(uint32_t*)&h0;
        *(uint32_t*)(smem + YSH_OFF + (r0 + 8) * YS + nc0 * 2) = *(uint32_t*)&h1;
        *(uint32_t*)(smem + YSL_OFF + r0 * YS + nc0 * 2)       = *(uint32_t*)&l0;
        *(uint32_t*)(smem + YSL_OFF + (r0 + 8) * YS + nc0 * 2) = *(uint32_t*)&l1;
    }

    // GEMM 2: K = 256 in 2 staged chunks
    #pragma unroll
    for (int t = 0; t < 16; t++)
        #pragma unroll
        for (int j = 0; j < 4; j++) acc[t][j] = 0.f;

    #pragma unroll 1
    for (int chunk = 0; chunk < 2; chunk++) {
        __syncthreads();
        #pragma unroll
        for (int i = 0; i < 32; i++) {
            int u = tid + i * 256;
            int half_ = u >> 12, r = (u >> 4) & 255, c = u & 15;
            const unsigned char* src =
                (const unsigned char*)(half_ ? (const void*)g_Wsl : (const void*)g_Wsh)
                + (size_t)r * 512 + chunk * 256 + c * 16;
            *(uint4*)(smem + W_OFF + half_ * WHL + r * WS + c * 16) = *(const uint4*)src;
        }
        __syncthreads();

        const unsigned char* Ah = smem + YSH_OFF + (16 * ms + g) * YS + chunk * 256 + kt * 4;
        const unsigned char* Al = smem + YSL_OFF + (16 * ms + g) * YS + chunk * 256 + kt * 4;
        const unsigned char* Bb = smem + W_OFF + (nh * 128 + g) * WS + kt * 4;
        #pragma unroll 1
        for (int ks = 0; ks < 8; ks++) {
            const int kb = ks * 32;
            uint32_t ah0 = *(const uint32_t*)(Ah + kb);
            uint32_t ah1 = *(const uint32_t*)(Ah + kb + 8 * YS);
            uint32_t ah2 = *(const uint32_t*)(Ah + kb + 16);
            uint32_t ah3 = *(const uint32_t*)(Ah + kb + 8 * YS + 16);
            uint32_t al0 = *(const uint32_t*)(Al + kb);
            uint32_t al1 = *(const uint32_t*)(Al + kb + 8 * YS);
            uint32_t al2 = *(const uint32_t*)(Al + kb + 16);
            uint32_t al3 = *(const uint32_t*)(Al + kb + 8 * YS + 16);
            #pragma unroll
            for (int t = 0; t < 16; t++) {
                const unsigned char* Bp = Bb + t * 8 * WS + kb;
                uint32_t bh0 = *(const uint32_t*)(Bp);
                uint32_t bh1 = *(const uint32_t*)(Bp + 16);
                uint32_t bl0 = *(const uint32_t*)(Bp + WHL);
                uint32_t bl1 = *(const uint32_t*)(Bp + WHL + 16);
                mma16816(acc[t], ah0, ah1, ah2, ah3, bh0, bh1);
                mma16816(acc[t], ah0, ah1, ah2, ah3, bl0, bl1);
                mma16816(acc[t], al0, al1, al2, al3, bh0, bh1);
            }
        }
    }

    // Final epilogue: e = exp(z), q = e*y; fp16 interleaved stores
    #pragma unroll
    for (int t = 0; t < 16; t++) {
        const int nc0 = nh * 128 + t * 8 + 2 * kt;
        const int r0 = 16 * ms + g;
        uint32_t yh0 = *(const uint32_t*)(smem + YSH_OFF + r0 * YS + nc0 * 2);
        uint32_t yl0 = *(const uint32_t*)(smem + YSL_OFF + r0 * YS + nc0 * 2);
        uint32_t yh1 = *(const uint32_t*)(smem + YSH_OFF + (r0 + 8) * YS + nc0 * 2);
        uint32_t yl1 = *(const uint32_t*)(smem + YSL_OFF + (r0 + 8) * YS + nc0 * 2);
        __nv_bfloat162 h0 = *(__nv_bfloat162*)&yh0, l0 = *(__nv_bfloat162*)&yl0;
        __nv_bfloat162 h1 = *(__nv_bfloat162*)&yh1, l1 = *(__nv_bfloat162*)&yl1;
        float y00 = __bfloat162float(h0.x) + __bfloat162float(l0.x);
        float y01 = __bfloat162float(h0.y) + __bfloat162float(l0.y);
        float y10 = __bfloat162float(h1.x) + __bfloat162float(l1.x);
        float y11 = __bfloat162float(h1.y) + __bfloat162float(l1.y);
        float e00 = __expf(acc[t][0]), e01 = __expf(acc[t][1]);
        float e10 = __expf(acc[t][2]), e11 = __expf(acc[t][3]);
        int gr0 = row0 + r0, gr1 = gr0 + 8;
        if (gr0 < N) {
            *(__half2*)(g_eq + (size_t)gr0 * 512 + nc0)       = __floats2half2_rn(e00, e01);
            *(__half2*)(g_eq + (size_t)gr0 * 512 + 256 + nc0) = __floats2half2_rn(e00 * y00, e01 * y01);
        }
        if (gr1 < N) {
            *(__half2*)(g_eq + (size_t)gr1 * 512 + nc0)       = __floats2half2_rn(e10, e11);
            *(__half2*)(g_eq + (size_t)gr1 * 512 + 256 + nc0) = __floats2half2_rn(e10 * y10, e11 * y11);
        }
    }
}

// ---------------------------------------------------------------------------
// kernelB1: gather only. Warp per node; 2 LDG.128 per neighbor; fp32 accum;
// feat = num/den -> bf16 hi/lo to global. No smem, no syncs.
// ---------------------------------------------------------------------------
__global__ __launch_bounds__(256) void kernelB1(
    const void* __restrict__ idxp, int N)
{
    const int wl   = threadIdx.x >> 5;
    const int lane = threadIdx.x & 31;
    const int n    = blockIdx.x * 8 + wl;
    if (n >= N) return;   // whole-warp exit (block may be partial only at end)

    const int is64 = g_idx64;

    int my = 0;
    if (lane < KNB) {
        if (is64) my = (int)((const long long*)idxp)[(size_t)n * KNB + lane];
        else      my = ((const int*)idxp)[(size_t)n * KNB + lane];
    }
    int nb[KNB];
    #pragma unroll
    for (int k = 0; k < KNB; k++)
        nb[k] = __shfl_sync(0xffffffffu, my, k);

    // Lane owns channels 8*lane .. 8*lane+7
    float den[8], num[8];
    #pragma unroll
    for (int q = 0; q < 8; q++) { den[q] = 0.f; num[q] = 0.f; }

    #pragma unroll 4
    for (int k = 0; k < KNB; k++) {
        const uint4* row = (const uint4*)(g_eq + (size_t)nb[k] * 512);
        uint4 ev = row[lane];        // e halves 8l..8l+7
        uint4 qv = row[32 + lane];   // q halves
        const __half2* eh = (const __half2*)&ev;
        const __half2* qh = (const __half2*)&qv;
        #pragma unroll
        for (int j = 0; j < 4; j++) {
            float2 fe = __half22float2(eh[j]);
            float2 fq = __half22float2(qh[j]);
            den[2*j]   += fe.x;  den[2*j+1] += fe.y;
            num[2*j]   += fq.x;  num[2*j+1] += fq.y;
        }
    }

    // feat = num/den -> bf16 hi/lo
    uint32_t hw[4], lw[4];
    #pragma unroll
    for (int j = 0; j < 4; j++) {
        float f0 = num[2*j]   / den[2*j];
        float f1 = num[2*j+1] / den[2*j+1];
        __nv_bfloat162 hh = __floats2bfloat162_rn(f0, f1);
        __nv_bfloat162 ll = __floats2bfloat162_rn(f0 - __bfloat162float(hh.x),
                                                  f1 - __bfloat162float(hh.y));
        hw[j] = *(uint32_t*)&hh;
        lw[j] = *(uint32_t*)&ll;
    }
    *(uint4*)(g_fh + (size_t)n * 256 + 8 * lane) = make_uint4(hw[0], hw[1], hw[2], hw[3]);
    *(uint4*)(g_fl + (size_t)n * 256 + 8 * lane) = make_uint4(lw[0], lw[1], lw[2], lw[3]);
}

// ---------------------------------------------------------------------------
// kernelC: out(64x128) = feat(64x256) @ Wm + bm, tensorized.
// Block = 64 rows, 8 warps: ms = M strip (16 rows), nh = N half (64 cols =
// 8 n8-tiles per warp). Wm chunk staged once per block (kills redundant
// per-warp Wm streaming). bf16 hi/lo 3-MMA split, fp32 accum.
// ---------------------------------------------------------------------------
__global__ __launch_bounds__(256, 1) void kernelC(
    const float* __restrict__ bm,
    float* __restrict__ out,
    int N)
{
    extern __shared__ unsigned char smem[];
    const int tid = threadIdx.x, wid = tid >> 5, lane = tid & 31;
    const int ms = wid & 3, nh = wid >> 2;
    const int g = lane >> 2, kt = lane & 3;
    const int row0 = blockIdx.x * 64;

    // Stage feat hi/lo: 64 rows x 512B each half, stride 528
    #pragma unroll
    for (int i = 0; i < 8; i++) {
        int t = tid + i * 256;            // 2048 uint4 per half
        int r = t >> 5, c = t & 31;
        int gr = row0 + r;
        uint4 vh = make_uint4(0, 0, 0, 0), vl = make_uint4(0, 0, 0, 0);
        if (gr < N) {
            vh = *(const uint4*)(g_fh + (size_t)gr * 256 + c * 8);
            vl = *(const uint4*)(g_fl + (size_t)gr * 256 + c * 8);
        }
        *(uint4*)(smem + C_FH + r * 528 + c * 16) = vh;
        *(uint4*)(smem + C_FL + r * 528 + c * 16) = vl;
    }

    float acc[8][4];
    #pragma unroll
    for (int t = 0; t < 8; t++)
        #pragma unroll
        for (int j = 0; j < 4; j++) acc[t][j] = 0.f;

    #pragma unroll 1
    for (int chunk = 0; chunk < 2; chunk++) {
        __syncthreads();   // covers feat staging (chunk 0) / prior reads (chunk 1)
        // Stage Wm chunk: 128 n-rows x 128 k (256B) per half, stride 272
        #pragma unroll
        for (int i = 0; i < 16; i++) {
            int u = tid + i * 256;        // 4096 uint4 (2048 per half)
            int half_ = u >> 11;
            int uu = u & 2047;
            int r = uu >> 4, c = uu & 15;
            const unsigned char* src =
                (const unsigned char*)(half_ ? (const void*)g_Wml : (const void*)g_Wmh)
                + (size_t)r * 512 + chunk * 256 + c * 16;
            *(uint4*)(smem + C_WH + half_ * 34816 + r * 272 + c * 16) = *(const uint4*)src;
        }
        __syncthreads();

        const unsigned char* Ah = smem + C_FH + (16 * ms + g) * 528 + chunk * 256 + kt * 4;
        const unsigned char* Al = smem + C_FL + (16 * ms + g) * 528 + chunk * 256 + kt * 4;
        const unsigned char* Bb = smem + C_WH + (nh * 64 + g) * 272 + kt * 4;
        #pragma unroll 1
        for (int ks = 0; ks < 8; ks++) {
            const int kb = ks * 32;
            uint32_t ah0 = *(const uint32_t*)(Ah + kb);
            uint32_t ah1 = *(const uint32_t*)(Ah + kb + 8 * 528);
            uint32_t ah2 = *(const uint32_t*)(Ah + kb + 16);
            uint32_t ah3 = *(const uint32_t*)(Ah + kb + 8 * 528 + 16);
            uint32_t al0 = *(const uint32_t*)(Al + kb);
            uint32_t al1 = *(const uint32_t*)(Al + kb + 8 * 528);
            uint32_t al2 = *(const uint32_t*)(Al + kb + 16);
            uint32_t al3 = *(const uint32_t*)(Al + kb + 8 * 528 + 16);
            #pragma unroll
            for (int t = 0; t < 8; t++) {
                const unsigned char* Bp = Bb + t * 8 * 272 + kb;
                uint32_t bh0 = *(const uint32_t*)(Bp);
                uint32_t bh1 = *(const uint32_t*)(Bp + 16);
                uint32_t bl0 = *(const uint32_t*)(Bp + 34816);
                uint32_t bl1 = *(const uint32_t*)(Bp + 34816 + 16);
                mma16816(acc[t], ah0, ah1, ah2, ah3, bh0, bh1);
                mma16816(acc[t], ah0, ah1, ah2, ah3, bl0, bl1);
                mma16816(acc[t], al0, al1, al2, al3, bh0, bh1);
            }
        }
    }

    // Epilogue: D rows = row0 + 16ms + g (+8); cols = nh*64 + t*8 + 2kt
    #pragma unroll
    for (int t = 0; t < 8; t++) {
        const int c0 = nh * 64 + t * 8 + 2 * kt;
        float2 bb = *(const float2*)(bm + c0);
        int n0 = row0 + 16 * ms + g;
        int n1 = n0 + 8;
        if (n0 < N)
            *(float2*)(out + (size_t)n0 * COUT + c0) =
                make_float2(acc[t][0] + bb.x, acc[t][1] + bb.y);
        if (n1 < N)
            *(float2*)(out + (size_t)n1 * COUT + c0) =
                make_float2(acc[t][2] + bb.x, acc[t][3] + bb.y);
    }
}

// ---------------------------------------------------------------------------
// Launch: memset(harness), prep, A, B1, C  -> ncu slot #5 = kernelB1
// ---------------------------------------------------------------------------
extern "C" void kernel_launch(void* const* d_in, const int* in_sizes, int n_in,
                              void* d_out, int out_size)
{
    const float* f     = (const float*)d_in[0];
    const void*  idxp  = (const void*) d_in[1];
    const float* W1    = (const float*)d_in[2];
    const float* b1    = (const float*)d_in[3];
    const float* gamma = (const float*)d_in[4];
    const float* beta  = (const float*)d_in[5];
    const float* rmean = (const float*)d_in[6];
    const float* rvar  = (const float*)d_in[7];
    const float* Ws    = (const float*)d_in[8];
    const float* Wm    = (const float*)d_in[9];
    const float* bm    = (const float*)d_in[10];
    float* out = (float*)d_out;

    const int N = in_sizes[0] / CIN;

    static int attr_set = 0;
    if (!attr_set) {
        cudaFuncSetAttribute(kernelA_mma,
                             cudaFuncAttributeMaxDynamicSharedMemorySize, SMEM_TOTAL);
        cudaFuncSetAttribute(kernelC,
                             cudaFuncAttributeMaxDynamicSharedMemorySize, C_SMEM);
        attr_set = 1;
    }

    prep_kernel<<<128, 256>>>(W1, Ws, Wm, (const unsigned int*)idxp);
    kernelA_mma<<<(N + 63) / 64, 256, SMEM_TOTAL>>>(f, b1, gamma, beta, rmean, rvar, N);
    kernelB1<<<(N + 7) / 8, 256>>>(idxp, N);
    kernelC<<<(N + 63) / 64, 256, C_SMEM>>>(bm, out, N);
}